// round 14
// baseline (speedup 1.0000x reference)
#include <cuda_runtime.h>
#include <cuda_bf16.h>
#include <cstdint>

#define B_      16
#define L_      2048
#define D_      512
#define H_      8
#define DH_     64
#define F_      2048
#define NL_     4
#define V_      21
#define TOKENS  (B_*L_)   // 32768

// ---------------- scratch ---------------------------------------------------
__device__ float g_h   [TOKENS * D_];
__device__ float g_qkv [(size_t)TOKENS * 3 * D_];
__device__ float g_o   [TOKENS * D_];
__device__ float g_t   [TOKENS * D_];
__device__ float g_ff  [(size_t)TOKENS * F_];
// tf32-rounded weights (B operands, native [K][N] layout)
__device__ float g_wqkv[(size_t)NL_ * D_ * 3 * D_];   // [512][1536] per layer
__device__ float g_wo  [(size_t)NL_ * D_ * D_];
__device__ float g_w1  [(size_t)NL_ * D_ * F_];
__device__ float g_w2  [(size_t)NL_ * F_ * D_];
__device__ float g_bqkv[NL_ * 3 * D_];

// ---------------- helpers ---------------------------------------------------
__device__ __forceinline__ float tf32r(float x) {
    uint32_t u; asm("cvt.rna.tf32.f32 %0, %1;" : "=r"(u) : "f"(x));
    return __uint_as_float(u);
}
__device__ __forceinline__ uint32_t smem_u32(const void* p) {
    uint32_t a;
    asm("{ .reg .u64 t; cvta.to.shared.u64 t, %1; cvt.u32.u64 %0, t; }" : "=r"(a) : "l"(p));
    return a;
}
__device__ __forceinline__ void cp16(uint32_t dst, const void* src) {
    asm volatile("cp.async.cg.shared.global [%0], [%1], 16;" :: "r"(dst), "l"(src));
}
__device__ __forceinline__ void cp_commit() {
    asm volatile("cp.async.commit_group;" ::: "memory");
}
__device__ __forceinline__ void mma1688(float* c, const uint32_t* a, const uint32_t* b) {
    asm volatile(
        "mma.sync.aligned.m16n8k8.row.col.f32.tf32.tf32.f32 "
        "{%0,%1,%2,%3}, {%4,%5,%6,%7}, {%8,%9}, {%0,%1,%2,%3};"
        : "+f"(c[0]), "+f"(c[1]), "+f"(c[2]), "+f"(c[3])
        : "r"(a[0]), "r"(a[1]), "r"(a[2]), "r"(a[3]), "r"(b[0]), "r"(b[1]));
}

// ---------------- tf32 mma.sync GEMM: C[M,N] = A[M,K] @ B[K,N] + bias -------
// CTA 128x256, 256 thr, warp 64x64 (2x4 warp grid), KC=32, double buffer.
// 1.0 LDS per MMA (vs 1.5 at 64x32) -> LDS-balanced with tensor pipe.
#define TM  128
#define TN  256
#define KC  32
#define AS_STRIDE 36     // floats per A smem row (32 + 4 pad)
#define BS_STRIDE 264    // floats per B smem row (256 + 8 pad)
#define A_BUF_BYTES (128 * AS_STRIDE * 4)   // 18432
#define B_BUF_BYTES (KC * BS_STRIDE * 4)    // 33792
#define SMEM_BYTES  (2 * A_BUF_BYTES + 2 * B_BUF_BYTES)  // 104448

__global__ __launch_bounds__(256) void gemm_mma(
    const float* __restrict__ A, const float* __restrict__ Bw,
    const float* __restrict__ bias, float* __restrict__ C,
    int M, int N, int K, int relu)
{
    extern __shared__ char smem[];
    const uint32_t sb = smem_u32(smem);
    const int tid  = threadIdx.x;
    const int wid  = tid >> 5;
    const int lane = tid & 31;
    const int gr   = lane >> 2;     // group (row) id
    const int tig  = lane & 3;      // thread-in-group
    const int wm   = wid >> 2;      // 0..1 (64-row slab)
    const int wn   = wid & 3;       // 0..3 (64-col slab)

    const uint32_t aOff[2] = {0u, (uint32_t)A_BUF_BYTES};
    const uint32_t bOff[2] = {(uint32_t)(2 * A_BUF_BYTES),
                              (uint32_t)(2 * A_BUF_BYTES + B_BUF_BYTES)};

    const float* Ab = A + (size_t)blockIdx.y * TM * K;
    const float* Bb = Bw + blockIdx.x * TN;
    const int nk = K / KC;

    // issue cp.async loads for chunk ch
    auto issue = [&](int ch) {
        const int s = ch & 1;
        const float* Ag = Ab + ch * KC;
        const float* Bg = Bb + (size_t)ch * KC * N;
        #pragma unroll
        for (int u = 0; u < 4; u++) {          // A: 128 rows x 8 float4
            int id = u * 256 + tid;
            int row = id >> 3, q = id & 7;
            cp16(sb + aOff[s] + (row * AS_STRIDE + q * 4) * 4,
                 Ag + (size_t)row * K + q * 4);
        }
        #pragma unroll
        for (int u = 0; u < 8; u++) {          // B: 32 rows x 64 float4
            int id = u * 256 + tid;
            int k = id >> 6, nq = id & 63;
            cp16(sb + bOff[s] + (k * BS_STRIDE + nq * 4) * 4,
                 Bg + (size_t)k * N + nq * 4);
        }
        cp_commit();
    };

    float acc[4][8][4];
    #pragma unroll
    for (int i = 0; i < 4; i++)
        #pragma unroll
        for (int j = 0; j < 8; j++)
            #pragma unroll
            for (int r = 0; r < 4; r++) acc[i][j][r] = 0.f;

    issue(0);
    issue(1);

    for (int i = 0; i < nk; i++) {
        if (i + 1 < nk) asm volatile("cp.async.wait_group 1;" ::: "memory");
        else            asm volatile("cp.async.wait_group 0;" ::: "memory");
        __syncthreads();

        const int s = i & 1;
        const float* As = (const float*)(smem + aOff[s]);
        const float* Bs = (const float*)(smem + bOff[s]);

        #pragma unroll
        for (int ks = 0; ks < 4; ks++) {
            const int k0 = ks * 8;
            uint32_t a[4][4], b[8][2];
            #pragma unroll
            for (int mt = 0; mt < 4; mt++) {
                int m = wm * 64 + mt * 16 + gr;
                a[mt][0] = __float_as_uint(As[m * AS_STRIDE + k0 + tig]);
                a[mt][1] = __float_as_uint(As[(m + 8) * AS_STRIDE + k0 + tig]);
                a[mt][2] = __float_as_uint(As[m * AS_STRIDE + k0 + tig + 4]);
                a[mt][3] = __float_as_uint(As[(m + 8) * AS_STRIDE + k0 + tig + 4]);
            }
            #pragma unroll
            for (int nt = 0; nt < 8; nt++) {
                int n = wn * 64 + nt * 8 + gr;
                b[nt][0] = __float_as_uint(Bs[(k0 + tig) * BS_STRIDE + n]);
                b[nt][1] = __float_as_uint(Bs[(k0 + tig + 4) * BS_STRIDE + n]);
            }
            #pragma unroll
            for (int mt = 0; mt < 4; mt++)
                #pragma unroll
                for (int nt = 0; nt < 8; nt++)
                    mma1688(acc[mt][nt], a[mt], b[nt]);
        }

        if (i + 2 < nk) {
            __syncthreads();
            issue(i + 2);
        }
    }

    // epilogue: bias + optional relu + tf32 round, direct float2 stores
    const int gm = blockIdx.y * TM;
    const int gn = blockIdx.x * TN;
    #pragma unroll
    for (int nt = 0; nt < 8; nt++) {
        const int col = gn + wn * 64 + nt * 8 + 2 * tig;
        const float2 bb = *(const float2*)(bias + col);
        #pragma unroll
        for (int mt = 0; mt < 4; mt++) {
            const int r0 = gm + wm * 64 + mt * 16 + gr;
            float v0 = acc[mt][nt][0] + bb.x;
            float v1 = acc[mt][nt][1] + bb.y;
            float v2 = acc[mt][nt][2] + bb.x;
            float v3 = acc[mt][nt][3] + bb.y;
            if (relu) {
                v0 = fmaxf(v0, 0.f); v1 = fmaxf(v1, 0.f);
                v2 = fmaxf(v2, 0.f); v3 = fmaxf(v3, 0.f);
            }
            float2 o0 = make_float2(tf32r(v0), tf32r(v1));
            float2 o1 = make_float2(tf32r(v2), tf32r(v3));
            *(float2*)(C + (size_t)r0 * N + col) = o0;
            *(float2*)(C + (size_t)(r0 + 8) * N + col) = o1;
        }
    }
}

// ---------------- weight prep (tf32 rounding) -------------------------------
__global__ void round_copy(const float* __restrict__ in, float* __restrict__ out, int n) {
    int i = blockIdx.x * 256 + threadIdx.x;
    if (i < n) out[i] = tf32r(in[i]);
}

__global__ void build_qkv_w(const float* __restrict__ Wq, const float* __restrict__ Wk,
                            const float* __restrict__ Wv, float* __restrict__ out) {
    int i = blockIdx.x * 256 + threadIdx.x;   // NL*512*1536
    int l = i / (512 * 1536), r = i % (512 * 1536);
    int k = r / 1536, n = r % 1536;
    const float* src = n < 512 ? Wq : (n < 1024 ? Wk : Wv);
    out[i] = tf32r(src[(size_t)l * 262144 + k * 512 + (n & 511)]);
}

__global__ void concat_bias(const float* __restrict__ bq, const float* __restrict__ bk,
                            const float* __restrict__ bv, float* __restrict__ out) {
    int i = blockIdx.x * 256 + threadIdx.x;   // NL*1536
    int l = i / 1536, j = i % 1536;
    out[i] = j < 512 ? bq[l * 512 + j]
           : (j < 1024 ? bk[l * 512 + j - 512] : bv[l * 512 + j - 1024]);
}

// ---------------- embedding -------------------------------------------------
__global__ void embed_kernel(const int* __restrict__ x, const float* __restrict__ tok,
                             const float* __restrict__ pos, float* __restrict__ h) {
    int i = blockIdx.x * blockDim.x + threadIdx.x;
    int d = i & (D_ - 1);
    int t = i >> 9;
    int l = t & (L_ - 1);
    h[i] = tf32r(tok[x[t] * D_ + d] + pos[l * D_ + d]);
}

// ---------------- 2-key tree attention (qkv fused buffer) -------------------
__global__ void attn_kernel(const float* __restrict__ qkv,
                            const int* __restrict__ parents,
                            float* __restrict__ o) {
    int warp = (blockIdx.x * blockDim.x + threadIdx.x) >> 5;
    int lane = threadIdx.x & 31;
    int h = warp & (H_ - 1);
    int t = warp >> 3;
    int l = t & (L_ - 1);
    int p = parents[l];

    const float* qp = qkv + (size_t)t * 1536 + h * DH_;
    const float* kp = qp + 512;
    float q0 = qp[lane], q1 = qp[lane + 32];

    float s0 = q0 * kp[lane] + q1 * kp[lane + 32];
    #pragma unroll
    for (int off = 16; off; off >>= 1) s0 += __shfl_xor_sync(~0u, s0, off);

    int pk = t;
    float a0 = 1.f, a1 = 0.f;
    if (p >= 0) {
        pk = t - l + (p + 1);
        const float* kpp = qkv + (size_t)pk * 1536 + 512 + h * DH_;
        float s1 = q0 * kpp[lane] + q1 * kpp[lane + 32];
        #pragma unroll
        for (int off = 16; off; off >>= 1) s1 += __shfl_xor_sync(~0u, s1, off);
        s0 *= 0.125f; s1 *= 0.125f;
        float m = fmaxf(s0, s1);
        float e0 = __expf(s0 - m), e1 = __expf(s1 - m);
        float inv = 1.f / (e0 + e1);
        a0 = e0 * inv; a1 = e1 * inv;
    }
    const float* vp  = qkv + (size_t)t  * 1536 + 1024 + h * DH_;
    const float* vpp = qkv + (size_t)pk * 1536 + 1024 + h * DH_;
    float* op = o + (size_t)t * D_ + h * DH_;
    op[lane]      = tf32r(a0 * vp[lane]      + a1 * vpp[lane]);
    op[lane + 32] = tf32r(a0 * vp[lane + 32] + a1 * vpp[lane + 32]);
}

// ---------------- residual add + LayerNorm (tf32-rounded output) ------------
__global__ void add_ln_kernel(float* __restrict__ h, const float* __restrict__ t,
                              const float* __restrict__ s, const float* __restrict__ b) {
    int row  = (blockIdx.x * blockDim.x + threadIdx.x) >> 5;
    int lane = threadIdx.x & 31;
    float* hp = h + (size_t)row * D_;
    const float* tp = t + (size_t)row * D_;

    float vals[16];
    float sum = 0.f;
    #pragma unroll
    for (int i = 0; i < 16; i++) {
        vals[i] = hp[lane + 32 * i] + tp[lane + 32 * i];
        sum += vals[i];
    }
    #pragma unroll
    for (int off = 16; off; off >>= 1) sum += __shfl_xor_sync(~0u, sum, off);
    float mu = sum * (1.f / 512.f);

    float var = 0.f;
    #pragma unroll
    for (int i = 0; i < 16; i++) { float d = vals[i] - mu; var += d * d; }
    #pragma unroll
    for (int off = 16; off; off >>= 1) var += __shfl_xor_sync(~0u, var, off);
    float inv = rsqrtf(var * (1.f / 512.f) + 1e-6f);

    #pragma unroll
    for (int i = 0; i < 16; i++) {
        int c = lane + 32 * i;
        hp[c] = tf32r((vals[i] - mu) * inv * s[c] + b[c]);
    }
}

// ---------------- final projection D=512 -> V=21 ----------------------------
__global__ void out_kernel(const float* __restrict__ h, const float* __restrict__ W,
                           const float* __restrict__ bias, float* __restrict__ out) {
    __shared__ float sh[D_];
    size_t row = blockIdx.x;
    const float* hp = h + row * D_;
    for (int i = threadIdx.x; i < D_; i += blockDim.x) sh[i] = hp[i];
    __syncthreads();
    int warp = threadIdx.x >> 5, lane = threadIdx.x & 31;
    for (int vv = warp; vv < V_; vv += 8) {
        float acc = 0.f;
        for (int d = lane; d < D_; d += 32) acc += sh[d] * W[d * V_ + vv];
        #pragma unroll
        for (int off = 16; off; off >>= 1) acc += __shfl_xor_sync(~0u, acc, off);
        if (lane == 0) out[row * V_ + vv] = acc + bias[vv];
    }
}

// ---------------------------------------------------------------------------
extern "C" void kernel_launch(void* const* d_in, const int* in_sizes, int n_in,
                              void* d_out, int out_size) {
    const int*   x       = (const int*)  d_in[0];
    const int*   parents = (const int*)  d_in[1];
    const float* tok     = (const float*)d_in[2];
    const float* pos     = (const float*)d_in[3];
    const float* Wq  = (const float*)d_in[4],  *bq = (const float*)d_in[5];
    const float* Wk  = (const float*)d_in[6],  *bk = (const float*)d_in[7];
    const float* Wv  = (const float*)d_in[8],  *bv = (const float*)d_in[9];
    const float* Wo  = (const float*)d_in[10], *bo = (const float*)d_in[11];
    const float* ln1s = (const float*)d_in[12], *ln1b = (const float*)d_in[13];
    const float* ln2s = (const float*)d_in[14], *ln2b = (const float*)d_in[15];
    const float* W1  = (const float*)d_in[16], *b1 = (const float*)d_in[17];
    const float* W2  = (const float*)d_in[18], *b2 = (const float*)d_in[19];
    const float* Wout = (const float*)d_in[20], *bout = (const float*)d_in[21];
    float* out = (float*)d_out;

    float *h, *qkv, *o, *t, *ff, *wqkv, *wo, *w1, *w2, *bqkv;
    cudaGetSymbolAddress((void**)&h,    g_h);
    cudaGetSymbolAddress((void**)&qkv,  g_qkv);
    cudaGetSymbolAddress((void**)&o,    g_o);
    cudaGetSymbolAddress((void**)&t,    g_t);
    cudaGetSymbolAddress((void**)&ff,   g_ff);
    cudaGetSymbolAddress((void**)&wqkv, g_wqkv);
    cudaGetSymbolAddress((void**)&wo,   g_wo);
    cudaGetSymbolAddress((void**)&w1,   g_w1);
    cudaGetSymbolAddress((void**)&w2,   g_w2);
    cudaGetSymbolAddress((void**)&bqkv, g_bqkv);

    cudaFuncSetAttribute(gemm_mma, cudaFuncAttributeMaxDynamicSharedMemorySize, SMEM_BYTES);

    // weight prep (tf32 rounding; small, part of the graph)
    build_qkv_w<<<NL_ * 512 * 1536 / 256, 256>>>(Wq, Wk, Wv, wqkv);
    round_copy<<<NL_ * 262144 / 256, 256>>>(Wo, wo, NL_ * 262144);
    round_copy<<<NL_ * 1048576 / 256, 256>>>(W1, w1, NL_ * 1048576);
    round_copy<<<NL_ * 1048576 / 256, 256>>>(W2, w2, NL_ * 1048576);
    concat_bias<<<NL_ * 1536 / 256, 256>>>(bq, bk, bv, bqkv);

    embed_kernel<<<TOKENS * D_ / 256, 256>>>(x, tok, pos, h);

    dim3 gQKV(1536 / TN, TOKENS / TM);   // (6, 256)
    dim3 gD  (512 / TN,  TOKENS / TM);   // (2, 256)
    dim3 gF  (F_ / TN,   TOKENS / TM);   // (8, 256)

    for (int l = 0; l < NL_; l++) {
        gemm_mma<<<gQKV, 256, SMEM_BYTES>>>(h, wqkv + (size_t)l * 786432,
                                            bqkv + l * 1536, qkv,
                                            TOKENS, 1536, 512, 0);
        attn_kernel<<<TOKENS * H_ * 32 / 256, 256>>>(qkv, parents, o);

        gemm_mma<<<gD, 256, SMEM_BYTES>>>(o, wo + (size_t)l * 262144,
                                          bo + l * D_, t, TOKENS, 512, 512, 0);
        add_ln_kernel<<<TOKENS * 32 / 256, 256>>>(h, t, ln1s + l * D_, ln1b + l * D_);

        gemm_mma<<<gF, 256, SMEM_BYTES>>>(h, w1 + (size_t)l * 1048576,
                                          b1 + l * F_, ff, TOKENS, F_, 512, 1);
        gemm_mma<<<gD, 256, SMEM_BYTES>>>(ff, w2 + (size_t)l * 1048576,
                                          b2 + l * D_, t, TOKENS, 512, 2048, 0);
        add_ln_kernel<<<TOKENS * 32 / 256, 256>>>(h, t, ln2s + l * D_, ln2b + l * D_);
    }

    out_kernel<<<TOKENS, 256>>>(h, Wout, bout, out);
}

// round 15
// speedup vs baseline: 1.6421x; 1.6421x over previous
#include <cuda_runtime.h>
#include <cuda_fp16.h>
#include <cstdint>

#define B_      16
#define L_      2048
#define D_      512
#define H_      8
#define DH_     64
#define F_      2048
#define NL_     4
#define V_      21
#define TOKENS  (B_*L_)   // 32768

// ---------------- scratch (fp16 activations + weights) ----------------------
__device__ __half g_h   [TOKENS * D_];
__device__ __half g_qkv [(size_t)TOKENS * 3 * D_];
__device__ __half g_o   [TOKENS * D_];
__device__ __half g_t   [TOKENS * D_];
__device__ __half g_ff  [(size_t)TOKENS * F_];
// half weights, transposed to [N][K] (K-major)
__device__ __half g_wqkv[(size_t)NL_ * 3 * D_ * D_];   // [1536][512] per layer
__device__ __half g_wo  [(size_t)NL_ * D_ * D_];       // [512][512]
__device__ __half g_w1  [(size_t)NL_ * F_ * D_];       // [2048][512]
__device__ __half g_w2  [(size_t)NL_ * D_ * F_];       // [512][2048]
__device__ float  g_bqkv[NL_ * 3 * D_];

// ---------------- helpers ---------------------------------------------------
__device__ __forceinline__ uint32_t smem_u32(const void* p) {
    uint32_t a;
    asm("{ .reg .u64 t; cvta.to.shared.u64 t, %1; cvt.u32.u64 %0, t; }" : "=r"(a) : "l"(p));
    return a;
}
__device__ __forceinline__ void cp16(uint32_t dst, const void* src) {
    asm volatile("cp.async.cg.shared.global [%0], [%1], 16;" :: "r"(dst), "l"(src));
}
__device__ __forceinline__ void cp_commit() {
    asm volatile("cp.async.commit_group;" ::: "memory");
}
__device__ __forceinline__ void mma16816(float* c, const uint32_t* a, const uint32_t* b) {
    asm volatile(
        "mma.sync.aligned.m16n8k16.row.col.f32.f16.f16.f32 "
        "{%0,%1,%2,%3}, {%4,%5,%6,%7}, {%8,%9}, {%0,%1,%2,%3};"
        : "+f"(c[0]), "+f"(c[1]), "+f"(c[2]), "+f"(c[3])
        : "r"(a[0]), "r"(a[1]), "r"(a[2]), "r"(a[3]), "r"(b[0]), "r"(b[1]));
}

// ---------------- fp16 mma.sync GEMM: C[M,N] = A[M,K] @ Bt[N,K]^T + bias ----
// CTA 128x256, 256 thr, warp 64x64 (2x4), KC=64 halves (4 k16-steps), dbl buf.
#define TM  128
#define TN  256
#define KC  64
#define AS_W 72    // halves per A smem row (64 + 8 pad) = 36 words
#define BS_W 72
#define A_BUF_BYTES (128 * AS_W * 2)   // 18432
#define B_BUF_BYTES (256 * BS_W * 2)   // 36864
#define SMEM_BYTES  (2 * A_BUF_BYTES + 2 * B_BUF_BYTES)  // 110592

__global__ __launch_bounds__(256) void gemm_mma(
    const __half* __restrict__ A, const __half* __restrict__ Bw,
    const float* __restrict__ bias, __half* __restrict__ C,
    int M, int N, int K, int relu)
{
    extern __shared__ char smem[];
    const uint32_t sb = smem_u32(smem);
    const int tid  = threadIdx.x;
    const int wid  = tid >> 5;
    const int lane = tid & 31;
    const int gr   = lane >> 2;
    const int tig  = lane & 3;
    const int wm   = wid >> 2;      // 0..1
    const int wn   = wid & 3;       // 0..3

    const uint32_t aOff[2] = {0u, (uint32_t)A_BUF_BYTES};
    const uint32_t bOff[2] = {(uint32_t)(2 * A_BUF_BYTES),
                              (uint32_t)(2 * A_BUF_BYTES + B_BUF_BYTES)};

    const __half* Ab = A + (size_t)blockIdx.y * TM * K;
    const __half* Bb = Bw + (size_t)blockIdx.x * TN * K;
    const int nk = K / KC;

    auto issue = [&](int ch) {
        const int s = ch & 1;
        const __half* Ag = Ab + ch * KC;
        const __half* Bg = Bb + ch * KC;
        #pragma unroll
        for (int u = 0; u < 4; u++) {          // A: 128 rows x 8 x (8 halves)
            int id = u * 256 + tid;
            int row = id >> 3, q = id & 7;
            cp16(sb + aOff[s] + (row * AS_W + q * 8) * 2,
                 Ag + (size_t)row * K + q * 8);
        }
        #pragma unroll
        for (int u = 0; u < 8; u++) {          // B: 256 rows x 8 x (8 halves)
            int id = u * 256 + tid;
            int row = id >> 3, q = id & 7;
            cp16(sb + bOff[s] + (row * BS_W + q * 8) * 2,
                 Bg + (size_t)row * K + q * 8);
        }
        cp_commit();
    };

    float acc[4][8][4];
    #pragma unroll
    for (int i = 0; i < 4; i++)
        #pragma unroll
        for (int j = 0; j < 8; j++)
            #pragma unroll
            for (int r = 0; r < 4; r++) acc[i][j][r] = 0.f;

    issue(0);
    issue(1);

    for (int i = 0; i < nk; i++) {
        if (i + 1 < nk) asm volatile("cp.async.wait_group 1;" ::: "memory");
        else            asm volatile("cp.async.wait_group 0;" ::: "memory");
        __syncthreads();

        const int s = i & 1;
        const uint32_t* Aw = (const uint32_t*)(smem + aOff[s]);
        const uint32_t* Bs = (const uint32_t*)(smem + bOff[s]);

        #pragma unroll
        for (int ks = 0; ks < 4; ks++) {
            const int kw = ks * 8;             // word offset of this k16 step
            uint32_t a[4][4], b[8][2];
            #pragma unroll
            for (int mt = 0; mt < 4; mt++) {
                int m = wm * 64 + mt * 16 + gr;
                a[mt][0] = Aw[m * 36 + kw + tig];
                a[mt][1] = Aw[(m + 8) * 36 + kw + tig];
                a[mt][2] = Aw[m * 36 + kw + 4 + tig];
                a[mt][3] = Aw[(m + 8) * 36 + kw + 4 + tig];
            }
            #pragma unroll
            for (int nt = 0; nt < 8; nt++) {
                int n = wn * 64 + nt * 8 + gr;
                b[nt][0] = Bs[n * 36 + kw + tig];
                b[nt][1] = Bs[n * 36 + kw + 4 + tig];
            }
            #pragma unroll
            for (int mt = 0; mt < 4; mt++)
                #pragma unroll
                for (int nt = 0; nt < 8; nt++)
                    mma16816(acc[mt][nt], a[mt], b[nt]);
        }

        if (i + 2 < nk) {
            __syncthreads();
            issue(i + 2);
        }
    }

    // epilogue: bias + optional relu, half2 stores
    const int gm = blockIdx.y * TM;
    const int gn = blockIdx.x * TN;
    #pragma unroll
    for (int nt = 0; nt < 8; nt++) {
        const int col = gn + wn * 64 + nt * 8 + 2 * tig;
        const float2 bb = *(const float2*)(bias + col);
        #pragma unroll
        for (int mt = 0; mt < 4; mt++) {
            const int r0 = gm + wm * 64 + mt * 16 + gr;
            float v0 = acc[mt][nt][0] + bb.x;
            float v1 = acc[mt][nt][1] + bb.y;
            float v2 = acc[mt][nt][2] + bb.x;
            float v3 = acc[mt][nt][3] + bb.y;
            if (relu) {
                v0 = fmaxf(v0, 0.f); v1 = fmaxf(v1, 0.f);
                v2 = fmaxf(v2, 0.f); v3 = fmaxf(v3, 0.f);
            }
            *(half2*)(C + (size_t)r0 * N + col)       = __floats2half2_rn(v0, v1);
            *(half2*)(C + (size_t)(r0 + 8) * N + col) = __floats2half2_rn(v2, v3);
        }
    }
}

// ---------------- weight prep: transpose fp32 [K][N] -> half [N][K] ---------
__global__ void transpose32h(const float* __restrict__ W, __half* __restrict__ T,
                             int K, int N) {
    __shared__ float s[32][33];
    int k0 = blockIdx.y * 32, n0 = blockIdx.x * 32;
    #pragma unroll
    for (int i = 0; i < 32; i += 8)
        s[threadIdx.y + i][threadIdx.x] =
            W[(size_t)(k0 + threadIdx.y + i) * N + n0 + threadIdx.x];
    __syncthreads();
    #pragma unroll
    for (int i = 0; i < 32; i += 8)
        T[(size_t)(n0 + threadIdx.y + i) * K + k0 + threadIdx.x] =
            __float2half(s[threadIdx.x][threadIdx.y + i]);
}

__global__ void concat_bias(const float* __restrict__ bq, const float* __restrict__ bk,
                            const float* __restrict__ bv, float* __restrict__ out) {
    int i = blockIdx.x * 256 + threadIdx.x;   // NL*1536
    int l = i / 1536, j = i % 1536;
    out[i] = j < 512 ? bq[l * 512 + j]
           : (j < 1024 ? bk[l * 512 + j - 512] : bv[l * 512 + j - 1024]);
}

// ---------------- embedding (fp16 output) ------------------------------------
__global__ void embed_kernel(const int* __restrict__ x, const float* __restrict__ tok,
                             const float* __restrict__ pos, __half* __restrict__ h) {
    int i = blockIdx.x * blockDim.x + threadIdx.x;
    int d = i & (D_ - 1);
    int t = i >> 9;
    int l = t & (L_ - 1);
    h[i] = __float2half(tok[x[t] * D_ + d] + pos[l * D_ + d]);
}

// ---------------- 2-key tree attention (fp16 buffers) ------------------------
__global__ void attn_kernel(const __half* __restrict__ qkv,
                            const int* __restrict__ parents,
                            __half* __restrict__ o) {
    int warp = (blockIdx.x * blockDim.x + threadIdx.x) >> 5;
    int lane = threadIdx.x & 31;
    int h = warp & (H_ - 1);
    int t = warp >> 3;
    int l = t & (L_ - 1);
    int p = parents[l];

    const __half* qp = qkv + (size_t)t * 1536 + h * DH_;
    const __half* kp = qp + 512;
    float q0 = __half2float(qp[lane]), q1 = __half2float(qp[lane + 32]);

    float s0 = q0 * __half2float(kp[lane]) + q1 * __half2float(kp[lane + 32]);
    #pragma unroll
    for (int off = 16; off; off >>= 1) s0 += __shfl_xor_sync(~0u, s0, off);

    int pk = t;
    float a0 = 1.f, a1 = 0.f;
    if (p >= 0) {
        pk = t - l + (p + 1);
        const __half* kpp = qkv + (size_t)pk * 1536 + 512 + h * DH_;
        float s1 = q0 * __half2float(kpp[lane]) + q1 * __half2float(kpp[lane + 32]);
        #pragma unroll
        for (int off = 16; off; off >>= 1) s1 += __shfl_xor_sync(~0u, s1, off);
        s0 *= 0.125f; s1 *= 0.125f;
        float m = fmaxf(s0, s1);
        float e0 = __expf(s0 - m), e1 = __expf(s1 - m);
        float inv = 1.f / (e0 + e1);
        a0 = e0 * inv; a1 = e1 * inv;
    }
    const __half* vp  = qkv + (size_t)t  * 1536 + 1024 + h * DH_;
    const __half* vpp = qkv + (size_t)pk * 1536 + 1024 + h * DH_;
    __half* op = o + (size_t)t * D_ + h * DH_;
    op[lane]      = __float2half(a0 * __half2float(vp[lane])      + a1 * __half2float(vpp[lane]));
    op[lane + 32] = __float2half(a0 * __half2float(vp[lane + 32]) + a1 * __half2float(vpp[lane + 32]));
}

// ---------------- residual add + LayerNorm (fp16 in/out, fp32 math) ---------
__global__ void add_ln_kernel(__half* __restrict__ h, const __half* __restrict__ t,
                              const float* __restrict__ s, const float* __restrict__ b) {
    int row  = (blockIdx.x * blockDim.x + threadIdx.x) >> 5;
    int lane = threadIdx.x & 31;
    __half* hp = h + (size_t)row * D_;
    const __half* tp = t + (size_t)row * D_;

    float vals[16];
    float sum = 0.f;
    #pragma unroll
    for (int i = 0; i < 16; i++) {
        vals[i] = __half2float(hp[lane + 32 * i]) + __half2float(tp[lane + 32 * i]);
        sum += vals[i];
    }
    #pragma unroll
    for (int off = 16; off; off >>= 1) sum += __shfl_xor_sync(~0u, sum, off);
    float mu = sum * (1.f / 512.f);

    float var = 0.f;
    #pragma unroll
    for (int i = 0; i < 16; i++) { float d = vals[i] - mu; var += d * d; }
    #pragma unroll
    for (int off = 16; off; off >>= 1) var += __shfl_xor_sync(~0u, var, off);
    float inv = rsqrtf(var * (1.f / 512.f) + 1e-6f);

    #pragma unroll
    for (int i = 0; i < 16; i++) {
        int c = lane + 32 * i;
        hp[c] = __float2half((vals[i] - mu) * inv * s[c] + b[c]);
    }
}

// ---------------- final projection D=512 -> V=21 (fp32 output) --------------
__global__ void out_kernel(const __half* __restrict__ h, const float* __restrict__ W,
                           const float* __restrict__ bias, float* __restrict__ out) {
    __shared__ float sh[D_];
    size_t row = blockIdx.x;
    const __half* hp = h + row * D_;
    for (int i = threadIdx.x; i < D_; i += blockDim.x) sh[i] = __half2float(hp[i]);
    __syncthreads();
    int warp = threadIdx.x >> 5, lane = threadIdx.x & 31;
    for (int vv = warp; vv < V_; vv += 8) {
        float acc = 0.f;
        for (int d = lane; d < D_; d += 32) acc += sh[d] * W[d * V_ + vv];
        #pragma unroll
        for (int off = 16; off; off >>= 1) acc += __shfl_xor_sync(~0u, acc, off);
        if (lane == 0) out[row * V_ + vv] = acc + bias[vv];
    }
}

// ---------------------------------------------------------------------------
extern "C" void kernel_launch(void* const* d_in, const int* in_sizes, int n_in,
                              void* d_out, int out_size) {
    const int*   x       = (const int*)  d_in[0];
    const int*   parents = (const int*)  d_in[1];
    const float* tok     = (const float*)d_in[2];
    const float* pos     = (const float*)d_in[3];
    const float* Wq  = (const float*)d_in[4],  *bq = (const float*)d_in[5];
    const float* Wk  = (const float*)d_in[6],  *bk = (const float*)d_in[7];
    const float* Wv  = (const float*)d_in[8],  *bv = (const float*)d_in[9];
    const float* Wo  = (const float*)d_in[10], *bo = (const float*)d_in[11];
    const float* ln1s = (const float*)d_in[12], *ln1b = (const float*)d_in[13];
    const float* ln2s = (const float*)d_in[14], *ln2b = (const float*)d_in[15];
    const float* W1  = (const float*)d_in[16], *b1 = (const float*)d_in[17];
    const float* W2  = (const float*)d_in[18], *b2 = (const float*)d_in[19];
    const float* Wout = (const float*)d_in[20], *bout = (const float*)d_in[21];
    float* out = (float*)d_out;

    __half *h, *qkv, *o, *t, *ff, *wqkv, *wo, *w1, *w2;
    float *bqkv;
    cudaGetSymbolAddress((void**)&h,    g_h);
    cudaGetSymbolAddress((void**)&qkv,  g_qkv);
    cudaGetSymbolAddress((void**)&o,    g_o);
    cudaGetSymbolAddress((void**)&t,    g_t);
    cudaGetSymbolAddress((void**)&ff,   g_ff);
    cudaGetSymbolAddress((void**)&wqkv, g_wqkv);
    cudaGetSymbolAddress((void**)&wo,   g_wo);
    cudaGetSymbolAddress((void**)&w1,   g_w1);
    cudaGetSymbolAddress((void**)&w2,   g_w2);
    cudaGetSymbolAddress((void**)&bqkv, g_bqkv);

    cudaFuncSetAttribute(gemm_mma, cudaFuncAttributeMaxDynamicSharedMemorySize, SMEM_BYTES);

    // weight transpose+convert to half [N][K] (part of the graph, small)
    dim3 tb(32, 8);
    for (int l = 0; l < NL_; l++) {
        transpose32h<<<dim3(16, 16), tb>>>(Wq + (size_t)l * 262144, wqkv + (size_t)l * 786432 + 0,      512, 512);
        transpose32h<<<dim3(16, 16), tb>>>(Wk + (size_t)l * 262144, wqkv + (size_t)l * 786432 + 262144, 512, 512);
        transpose32h<<<dim3(16, 16), tb>>>(Wv + (size_t)l * 262144, wqkv + (size_t)l * 786432 + 524288, 512, 512);
        transpose32h<<<dim3(16, 16), tb>>>(Wo + (size_t)l * 262144, wo + (size_t)l * 262144, 512, 512);
        transpose32h<<<dim3(64, 16), tb>>>(W1 + (size_t)l * 1048576, w1 + (size_t)l * 1048576, 512, 2048);
        transpose32h<<<dim3(16, 64), tb>>>(W2 + (size_t)l * 1048576, w2 + (size_t)l * 1048576, 2048, 512);
    }
    concat_bias<<<NL_ * 1536 / 256, 256>>>(bq, bk, bv, bqkv);

    embed_kernel<<<TOKENS * D_ / 256, 256>>>(x, tok, pos, h);

    dim3 gQKV(1536 / TN, TOKENS / TM);   // (6, 256)
    dim3 gD  (512 / TN,  TOKENS / TM);   // (2, 256)
    dim3 gF  (F_ / TN,   TOKENS / TM);   // (8, 256)

    for (int l = 0; l < NL_; l++) {
        gemm_mma<<<gQKV, 256, SMEM_BYTES>>>(h, wqkv + (size_t)l * 786432,
                                            bqkv + l * 1536, qkv,
                                            TOKENS, 1536, 512, 0);
        attn_kernel<<<TOKENS * H_ * 32 / 256, 256>>>(qkv, parents, o);

        gemm_mma<<<gD, 256, SMEM_BYTES>>>(o, wo + (size_t)l * 262144,
                                          bo + l * D_, t, TOKENS, 512, 512, 0);
        add_ln_kernel<<<TOKENS * 32 / 256, 256>>>(h, t, ln1s + l * D_, ln1b + l * D_);

        gemm_mma<<<gF, 256, SMEM_BYTES>>>(h, w1 + (size_t)l * 1048576,
                                          b1 + l * F_, ff, TOKENS, F_, 512, 1);
        gemm_mma<<<gD, 256, SMEM_BYTES>>>(ff, w2 + (size_t)l * 1048576,
                                          b2 + l * D_, t, TOKENS, 512, 2048, 0);
        add_ln_kernel<<<TOKENS * 32 / 256, 256>>>(h, t, ln2s + l * D_, ln2b + l * D_);
    }

    out_kernel<<<TOKENS, 256>>>(h, Wout, bout, out);
}